// round 15
// baseline (speedup 1.0000x reference)
#include <cuda_runtime.h>
#include <cuda_fp16.h>
#include <cstdint>

#define BATCH 2
#define SEQ   2048
#define NH    16
#define DHD   64
#define EMB   1024

__device__ __align__(256) __half g_x[BATCH*SEQ*EMB];
__device__ __align__(256) __half g_w[3*EMB*EMB];
__device__ __align__(256) __half g_q[BATCH*NH*SEQ*DHD];
__device__ __align__(256) __half g_k[BATCH*NH*SEQ*DHD];
__device__ __align__(256) __half g_v[BATCH*NH*SEQ*DHD];

#define SW(o) ((uint32_t)(o) ^ ((((uint32_t)(o))>>3)&0x70))

__device__ __forceinline__ uint32_t smem_u32(const void* p){
    uint32_t a;
    asm("{ .reg .u64 t; cvta.to.shared.u64 t, %1; cvt.u32.u64 %0, t; }" : "=r"(a) : "l"(p));
    return a;
}
__device__ __forceinline__ void ldsm4(uint32_t* r, uint32_t a){
    asm volatile("ldmatrix.sync.aligned.m8n8.x4.shared.b16 {%0,%1,%2,%3}, [%4];"
        : "=r"(r[0]),"=r"(r[1]),"=r"(r[2]),"=r"(r[3]) : "r"(a));
}
__device__ __forceinline__ void ldsm4t(uint32_t* r, uint32_t a){
    asm volatile("ldmatrix.sync.aligned.m8n8.x4.trans.shared.b16 {%0,%1,%2,%3}, [%4];"
        : "=r"(r[0]),"=r"(r[1]),"=r"(r[2]),"=r"(r[3]) : "r"(a));
}
__device__ __forceinline__ void mmah(float* c, const uint32_t* a, const uint32_t* b){
    asm volatile("mma.sync.aligned.m16n8k16.row.col.f32.f16.f16.f32 "
        "{%0,%1,%2,%3}, {%4,%5,%6,%7}, {%8,%9}, {%0,%1,%2,%3};"
        : "+f"(c[0]),"+f"(c[1]),"+f"(c[2]),"+f"(c[3])
        : "r"(a[0]),"r"(a[1]),"r"(a[2]),"r"(a[3]), "r"(b[0]),"r"(b[1]));
}
__device__ __forceinline__ void cpa(uint32_t dst, const void* src){
    asm volatile("cp.async.cg.shared.global [%0], [%1], 16;" :: "r"(dst), "l"(src));
}
__device__ __forceinline__ void cpcommit(){ asm volatile("cp.async.commit_group;" ::: "memory"); }
template<int N> __device__ __forceinline__ void cpwait(){
    asm volatile("cp.async.wait_group %0;" :: "n"(N) : "memory");
}
__device__ __forceinline__ uint32_t ex2h2(uint32_t x){
    uint32_t r; asm("ex2.approx.f16x2 %0, %1;" : "=r"(r) : "r"(x)); return r;
}
__device__ __forceinline__ uint32_t pkh(float a, float b){
    __half2 t = __floats2half2_rn(a, b);
    return *(uint32_t*)&t;
}

// ============================================================================
// Single converter launch: y=0..3 -> quarters of x, y=4..6 -> Wq/Wk/Wv
// ============================================================================
__global__ __launch_bounds__(256) void cvt_all(
    const float* __restrict__ x,
    const float* __restrict__ w0, const float* __restrict__ w1, const float* __restrict__ w2,
    __half* __restrict__ dx, __half* __restrict__ dw)
{
    const int y = blockIdx.y;
    const size_t i = (size_t)blockIdx.x*256 + threadIdx.x;
    const float* s;
    __half* d;
    if (y < 4) { s = x + (size_t)y*1048576;  d = dx + (size_t)y*1048576; }
    else if (y == 4) { s = w0; d = dw; }
    else if (y == 5) { s = w1; d = dw + (size_t)EMB*EMB; }
    else             { s = w2; d = dw + (size_t)2*EMB*EMB; }
    float4 v = ((const float4*)s)[i];
    ((uint2*)d)[i] = make_uint2(pkh(v.x,v.y), pkh(v.z,v.w));
}

// ============================================================================
// QKV GEMM (unchanged). grid=(8,32,3), 128 thr, 2 CTAs/SM, 64KB smem.
// ============================================================================
#define G_SMEM (2*32768)

__global__ __launch_bounds__(128,2) void qkv_gemm()
{
    extern __shared__ char smem[];
    const uint32_t sb = smem_u32(smem);
    const int tid = threadIdx.x, lane = tid&31, wid = tid>>5;
    const int z = blockIdx.z;
    const int row0 = blockIdx.y*128, col0 = blockIdx.x*128;
    const int wm = wid>>1, wn = wid&1, m0 = wm*64;
    const size_t wofs = (size_t)z*EMB*EMB;

    float acc[4][8][4];
    #pragma unroll
    for (int a=0;a<4;a++) for (int b=0;b<8;b++) for (int c=0;c<4;c++) acc[a][b][c]=0.f;

    auto issue = [&](int kc){
        uint32_t base = sb + (kc&1)*32768;
        #pragma unroll
        for (int it=0; it<8; it++) {
            int i = tid + it*128;
            int r = i>>3, c8 = (i&7)*8;
            cpa(base + SW(r*128 + c8*2), g_x + (size_t)(row0+r)*EMB + kc*64 + c8);
        }
        #pragma unroll
        for (int it=0; it<8; it++) {
            int i = tid + it*128;
            int k = i>>4, n8 = (i&15)*8;
            uint32_t off = 16384 + (n8>>6)*8192 + SW(k*128 + (n8&63)*2);
            cpa(base + off, g_w + wofs + (size_t)(kc*64+k)*EMB + col0 + n8);
        }
        cpcommit();
    };

    issue(0);
    for (int kc=0; kc<16; kc++) {
        if (kc<15) { issue(kc+1); cpwait<1>(); } else cpwait<0>();
        __syncthreads();

        const uint32_t sa = sb + (kc&1)*32768;
        const uint32_t b_base = sa + 16384 + wn*8192;
        #pragma unroll
        for (int ks=0; ks<4; ks++) {
            uint32_t af[4][4];
            #pragma unroll
            for (int mt=0; mt<4; mt++) {
                uint32_t ao = (uint32_t)((m0 + mt*16 + (lane&7) + ((lane>>3)&1)*8)*128
                                          + ks*32 + ((lane>>4)&1)*16);
                ldsm4(af[mt], sa + SW(ao));
            }
            #pragma unroll
            for (int pr=0; pr<4; pr++) {
                uint32_t bf[4];
                uint32_t bo = (uint32_t)((ks*16 + (lane&7) + ((lane>>3)&1)*8)*128
                                          + pr*32 + ((lane>>4)&1)*16);
                ldsm4t(bf, b_base + SW(bo));
                #pragma unroll
                for (int mt=0; mt<4; mt++) {
                    mmah(acc[mt][2*pr],   af[mt], bf);
                    mmah(acc[mt][2*pr+1], af[mt], bf+2);
                }
            }
        }
        __syncthreads();
    }

    const int g = lane>>2, q = lane&3;
    __half* dst = (z==0)? g_q : (z==1)? g_k : g_v;
    const float scale = (z==0)? 0.125f*1.44269504f : 1.0f;
    const int hgl = (col0>>6) + wn;
    #pragma unroll
    for (int mt=0; mt<4; mt++) {
        #pragma unroll
        for (int hf=0; hf<2; hf++) {
            int row = row0 + m0 + mt*16 + g + hf*8;
            int bb = row>>11, n = row&(SEQ-1);
            size_t base = (((size_t)(bb*NH + hgl))*SEQ + n)*DHD;
            #pragma unroll
            for (int nt=0; nt<8; nt++) {
                int dh = nt*8 + q*2;
                *(uint32_t*)(dst + base + dh) =
                    pkh(acc[mt][nt][hf*2+0]*scale, acc[mt][nt][hf*2+1]*scale);
            }
        }
    }
}

// ============================================================================
// Flash attention. grid=(32,16,2), 128 thr (4 warps = 2wm x 2wn), 3 CTAs/SM.
// Tile loop restructured per-16-kv-chunk: S-MMA -> exp -> PV per chunk, so
// chunk c+1's S-MMAs overlap chunk c's exp/PV (fills the tensor bubble), and
// the live s-register set shrinks from 64 to 16 floats (fits 170-reg cap).
// smem 72KB: Q@0 (8KB); 2 K/V stages @8K (k@0, v@16K per 32KB stage).
// ============================================================================
#define A_SMEM (8192 + 2*32768)

__global__ __launch_bounds__(128,3) void attn(float* __restrict__ out)
{
    extern __shared__ char smem[];
    const uint32_t sb = smem_u32(smem);
    const int tid = threadIdx.x, lane = tid&31, wid = tid>>5;
    const int b = blockIdx.z, h = blockIdx.y, q0 = blockIdx.x*64;
    const size_t hb = ((size_t)(b*NH + h))*SEQ;
    const int wm = wid>>1, wn = wid&1, m0 = wm*32;
    const uint32_t nb = wn*64*128;

    auto issueKV = [&](int kt){
        uint32_t base = sb + 8192 + (kt&1)*32768;
        const int k0 = kt*128;
        #pragma unroll
        for (int it=0; it<8; it++) {
            int i = tid + it*128;
            int r = i>>3, c8 = (i&7)*8;
            uint32_t off = SW(r*128 + c8*2);
            size_t gofs = (hb + k0 + r)*DHD + c8;
            cpa(base + off,         g_k + gofs);
            cpa(base + 16384 + off, g_v + gofs);
        }
        cpcommit();
    };

    issueKV(0);
    #pragma unroll
    for (int it=0; it<4; it++) {               // Q tile: 64 rows (8KB)
        int i = tid + it*128;
        int r = i>>3, c8 = (i&7)*8;
        *(uint4*)(smem + SW(r*128 + c8*2)) = *(const uint4*)(g_q + (hb+q0+r)*DHD + c8);
    }
    __syncthreads();

    uint32_t qf[2][4][4];
    #pragma unroll
    for (int mt=0; mt<2; mt++)
        #pragma unroll
        for (int ks=0; ks<4; ks++) {
            uint32_t ao = (uint32_t)((m0 + mt*16 + (lane&7) + ((lane>>3)&1)*8)*128
                                      + ks*32 + ((lane>>4)&1)*16);
            ldsm4(qf[mt][ks], sb + SW(ao));
        }

    float o[2][8][4];
    #pragma unroll
    for (int m=0;m<2;m++) for (int a=0;a<8;a++) for (int c=0;c<4;c++) o[m][a][c]=0.f;
    float rs[2][2] = {{0.f,0.f},{0.f,0.f}};

    for (int kt=0; kt<16; kt++) {
        if (kt<15) { issueKV(kt+1); cpwait<1>(); } else cpwait<0>();
        __syncthreads();
        const uint32_t sk = sb + 8192 + (kt&1)*32768;

        // Per 16-kv-column chunk: S-MMA -> exp/pack -> PV. Chunks independent.
        #pragma unroll
        for (int c=0; c<4; c++) {
            // S for this chunk (16 kv cols), both mt halves
            float s[2][2][4];
            #pragma unroll
            for (int m=0;m<2;m++) for (int a=0;a<2;a++) for (int e=0;e<4;e++) s[m][a][e]=0.f;
            #pragma unroll
            for (int ksd=0; ksd<4; ksd++) {
                uint32_t kf[4];
                uint32_t bo = (uint32_t)(nb + (c*16 + (lane&7) + ((lane>>4)&1)*8)*128
                                          + ksd*32 + ((lane>>3)&1)*16);
                ldsm4(kf, sk + SW(bo));
                #pragma unroll
                for (int mt=0; mt<2; mt++) {
                    mmah(s[mt][0], qf[mt][ksd], kf);
                    mmah(s[mt][1], qf[mt][ksd], kf+2);
                }
            }
            // exp/pack + rowsum (HADD2 tree, off the tensor pipe)
            uint32_t pf[2][4];
            #pragma unroll
            for (int mt=0; mt<2; mt++) {
                pf[mt][0] = ex2h2(pkh(s[mt][0][0], s[mt][0][1]));
                pf[mt][1] = ex2h2(pkh(s[mt][0][2], s[mt][0][3]));
                pf[mt][2] = ex2h2(pkh(s[mt][1][0], s[mt][1][1]));
                pf[mt][3] = ex2h2(pkh(s[mt][1][2], s[mt][1][3]));
                __half2 hg  = __hadd2(*(__half2*)&pf[mt][0], *(__half2*)&pf[mt][2]);
                __half2 hg8 = __hadd2(*(__half2*)&pf[mt][1], *(__half2*)&pf[mt][3]);
                float2 fg  = __half22float2(hg);
                float2 fg8 = __half22float2(hg8);
                rs[mt][0] += fg.x  + fg.y;
                rs[mt][1] += fg8.x + fg8.y;
            }
            // PV for this chunk's 16 kv rows, all 64 dh columns
            #pragma unroll
            for (int pr=0; pr<4; pr++) {
                uint32_t vf[4];
                uint32_t vo = (uint32_t)(nb + (c*16 + (lane&7) + ((lane>>3)&1)*8)*128
                                          + pr*32 + ((lane>>4)&1)*16);
                ldsm4t(vf, sk + 16384 + SW(vo));
                #pragma unroll
                for (int mt=0; mt<2; mt++) {
                    mmah(o[mt][2*pr],   pf[mt], vf);
                    mmah(o[mt][2*pr+1], pf[mt], vf+2);
                }
            }
        }
        __syncthreads();
    }

    // ---- quad reduction of rowsums, then combine across the wn pair ----
    #pragma unroll
    for (int mt=0; mt<2; mt++) {
        rs[mt][0] += __shfl_xor_sync(0xffffffffu, rs[mt][0], 1);
        rs[mt][0] += __shfl_xor_sync(0xffffffffu, rs[mt][0], 2);
        rs[mt][1] += __shfl_xor_sync(0xffffffffu, rs[mt][1], 1);
        rs[mt][1] += __shfl_xor_sync(0xffffffffu, rs[mt][1], 2);
    }

    const int g = lane>>2, q = lane&3;
    float* rsArr = (float*)smem;                        // [2][64] (Q region, done)
    float* Osum  = (float*)(smem + 8192) + wm*2048;     // per-wm [32][64] floats
    if ((lane&3)==0) {
        #pragma unroll
        for (int mt=0; mt<2; mt++) {
            rsArr[wn*64 + m0 + mt*16 + g]     = rs[mt][0];
            rsArr[wn*64 + m0 + mt*16 + 8 + g] = rs[mt][1];
        }
    }
    if (wn==1) {
        #pragma unroll
        for (int mt=0; mt<2; mt++)
            #pragma unroll
            for (int nt=0; nt<8; nt++) {
                *(float2*)&Osum[(mt*16+g)*64   + nt*8 + q*2] = make_float2(o[mt][nt][0], o[mt][nt][1]);
                *(float2*)&Osum[(mt*16+g+8)*64 + nt*8 + q*2] = make_float2(o[mt][nt][2], o[mt][nt][3]);
            }
    }
    __syncthreads();
    if (wn==0) {
        #pragma unroll
        for (int mt=0; mt<2; mt++) {
            const int r0 = m0 + mt*16 + g;
            const float i0 = 1.0f/(rsArr[r0]     + rsArr[64+r0]);
            const float i1 = 1.0f/(rsArr[r0+8]   + rsArr[64+r0+8]);
            float* op0 = out + ((size_t)b*SEQ + q0 + r0)*EMB + h*DHD;
            float* op1 = op0 + (size_t)8*EMB;
            #pragma unroll
            for (int nt=0; nt<8; nt++) {
                int dh = nt*8 + q*2;
                float2 v0 = *(float2*)&Osum[(mt*16+g)*64   + dh];
                float2 v1 = *(float2*)&Osum[(mt*16+g+8)*64 + dh];
                *(float2*)(op0 + dh) = make_float2((o[mt][nt][0]+v0.x)*i0, (o[mt][nt][1]+v0.y)*i0);
                *(float2*)(op1 + dh) = make_float2((o[mt][nt][2]+v1.x)*i1, (o[mt][nt][3]+v1.y)*i1);
            }
        }
    }
}

// ---------------------------------------------------------------------------
extern "C" void kernel_launch(void* const* d_in, const int* in_sizes, int n_in,
                              void* d_out, int out_size)
{
    const float* x  = (const float*)d_in[0];
    const float* wq = (const float*)d_in[1];
    const float* wk = (const float*)d_in[2];
    const float* wv = (const float*)d_in[3];
    float* out = (float*)d_out;

    cudaFuncSetAttribute(qkv_gemm, cudaFuncAttributeMaxDynamicSharedMemorySize, G_SMEM);
    cudaFuncSetAttribute(attn,     cudaFuncAttributeMaxDynamicSharedMemorySize, A_SMEM);

    __half *xp, *wp;
    cudaGetSymbolAddress((void**)&xp, g_x);
    cudaGetSymbolAddress((void**)&wp, g_w);

    dim3 gc(1024, 7);
    cvt_all<<<gc, 256>>>(x, wq, wk, wv, xp, wp);

    dim3 gg(EMB/128, (BATCH*SEQ)/128, 3);
    qkv_gemm<<<gg, 128, G_SMEM>>>();

    dim3 ga(SEQ/64, NH, BATCH);
    attn<<<ga, 128, A_SMEM>>>(out);
}

// round 16
// speedup vs baseline: 1.0386x; 1.0386x over previous
#include <cuda_runtime.h>
#include <cuda_fp16.h>
#include <cstdint>

#define BATCH 2
#define SEQ   2048
#define NH    16
#define DHD   64
#define EMB   1024

__device__ __align__(256) __half g_x[BATCH*SEQ*EMB];
__device__ __align__(256) __half g_w[3*EMB*EMB];
__device__ __align__(256) __half g_q[BATCH*NH*SEQ*DHD];
__device__ __align__(256) __half g_k[BATCH*NH*SEQ*DHD];
__device__ __align__(256) __half g_v[BATCH*NH*SEQ*DHD];

#define SW(o) ((uint32_t)(o) ^ ((((uint32_t)(o))>>3)&0x70))

__device__ __forceinline__ uint32_t smem_u32(const void* p){
    uint32_t a;
    asm("{ .reg .u64 t; cvta.to.shared.u64 t, %1; cvt.u32.u64 %0, t; }" : "=r"(a) : "l"(p));
    return a;
}
__device__ __forceinline__ void ldsm4(uint32_t* r, uint32_t a){
    asm volatile("ldmatrix.sync.aligned.m8n8.x4.shared.b16 {%0,%1,%2,%3}, [%4];"
        : "=r"(r[0]),"=r"(r[1]),"=r"(r[2]),"=r"(r[3]) : "r"(a));
}
__device__ __forceinline__ void ldsm4t(uint32_t* r, uint32_t a){
    asm volatile("ldmatrix.sync.aligned.m8n8.x4.trans.shared.b16 {%0,%1,%2,%3}, [%4];"
        : "=r"(r[0]),"=r"(r[1]),"=r"(r[2]),"=r"(r[3]) : "r"(a));
}
__device__ __forceinline__ void mmah(float* c, const uint32_t* a, const uint32_t* b){
    asm volatile("mma.sync.aligned.m16n8k16.row.col.f32.f16.f16.f32 "
        "{%0,%1,%2,%3}, {%4,%5,%6,%7}, {%8,%9}, {%0,%1,%2,%3};"
        : "+f"(c[0]),"+f"(c[1]),"+f"(c[2]),"+f"(c[3])
        : "r"(a[0]),"r"(a[1]),"r"(a[2]),"r"(a[3]), "r"(b[0]),"r"(b[1]));
}
__device__ __forceinline__ void cpa(uint32_t dst, const void* src){
    asm volatile("cp.async.cg.shared.global [%0], [%1], 16;" :: "r"(dst), "l"(src));
}
__device__ __forceinline__ void cpcommit(){ asm volatile("cp.async.commit_group;" ::: "memory"); }
template<int N> __device__ __forceinline__ void cpwait(){
    asm volatile("cp.async.wait_group %0;" :: "n"(N) : "memory");
}
__device__ __forceinline__ uint32_t ex2h2(uint32_t x){
    uint32_t r; asm("ex2.approx.f16x2 %0, %1;" : "=r"(r) : "r"(x)); return r;
}
__device__ __forceinline__ uint32_t pkh(float a, float b){
    __half2 t = __floats2half2_rn(a, b);
    return *(uint32_t*)&t;
}

// ============================================================================
// Single converter launch: y=0..3 -> quarters of x, y=4..6 -> Wq/Wk/Wv
// ============================================================================
__global__ __launch_bounds__(256) void cvt_all(
    const float* __restrict__ x,
    const float* __restrict__ w0, const float* __restrict__ w1, const float* __restrict__ w2,
    __half* __restrict__ dx, __half* __restrict__ dw)
{
    const int y = blockIdx.y;
    const size_t i = (size_t)blockIdx.x*256 + threadIdx.x;
    const float* s;
    __half* d;
    if (y < 4) { s = x + (size_t)y*1048576;  d = dx + (size_t)y*1048576; }
    else if (y == 4) { s = w0; d = dw; }
    else if (y == 5) { s = w1; d = dw + (size_t)EMB*EMB; }
    else             { s = w2; d = dw + (size_t)2*EMB*EMB; }
    float4 v = ((const float4*)s)[i];
    ((uint2*)d)[i] = make_uint2(pkh(v.x,v.y), pkh(v.z,v.w));
}

// ============================================================================
// QKV GEMM (unchanged). grid=(8,32,3), 128 thr, 2 CTAs/SM, 64KB smem.
// ============================================================================
#define G_SMEM (2*32768)

__global__ __launch_bounds__(128,2) void qkv_gemm()
{
    extern __shared__ char smem[];
    const uint32_t sb = smem_u32(smem);
    const int tid = threadIdx.x, lane = tid&31, wid = tid>>5;
    const int z = blockIdx.z;
    const int row0 = blockIdx.y*128, col0 = blockIdx.x*128;
    const int wm = wid>>1, wn = wid&1, m0 = wm*64;
    const size_t wofs = (size_t)z*EMB*EMB;

    float acc[4][8][4];
    #pragma unroll
    for (int a=0;a<4;a++) for (int b=0;b<8;b++) for (int c=0;c<4;c++) acc[a][b][c]=0.f;

    auto issue = [&](int kc){
        uint32_t base = sb + (kc&1)*32768;
        #pragma unroll
        for (int it=0; it<8; it++) {
            int i = tid + it*128;
            int r = i>>3, c8 = (i&7)*8;
            cpa(base + SW(r*128 + c8*2), g_x + (size_t)(row0+r)*EMB + kc*64 + c8);
        }
        #pragma unroll
        for (int it=0; it<8; it++) {
            int i = tid + it*128;
            int k = i>>4, n8 = (i&15)*8;
            uint32_t off = 16384 + (n8>>6)*8192 + SW(k*128 + (n8&63)*2);
            cpa(base + off, g_w + wofs + (size_t)(kc*64+k)*EMB + col0 + n8);
        }
        cpcommit();
    };

    issue(0);
    for (int kc=0; kc<16; kc++) {
        if (kc<15) { issue(kc+1); cpwait<1>(); } else cpwait<0>();
        __syncthreads();

        const uint32_t sa = sb + (kc&1)*32768;
        const uint32_t b_base = sa + 16384 + wn*8192;
        #pragma unroll
        for (int ks=0; ks<4; ks++) {
            uint32_t af[4][4];
            #pragma unroll
            for (int mt=0; mt<4; mt++) {
                uint32_t ao = (uint32_t)((m0 + mt*16 + (lane&7) + ((lane>>3)&1)*8)*128
                                          + ks*32 + ((lane>>4)&1)*16);
                ldsm4(af[mt], sa + SW(ao));
            }
            #pragma unroll
            for (int pr=0; pr<4; pr++) {
                uint32_t bf[4];
                uint32_t bo = (uint32_t)((ks*16 + (lane&7) + ((lane>>3)&1)*8)*128
                                          + pr*32 + ((lane>>4)&1)*16);
                ldsm4t(bf, b_base + SW(bo));
                #pragma unroll
                for (int mt=0; mt<4; mt++) {
                    mmah(acc[mt][2*pr],   af[mt], bf);
                    mmah(acc[mt][2*pr+1], af[mt], bf+2);
                }
            }
        }
        __syncthreads();
    }

    const int g = lane>>2, q = lane&3;
    __half* dst = (z==0)? g_q : (z==1)? g_k : g_v;
    const float scale = (z==0)? 0.125f*1.44269504f : 1.0f;
    const int hgl = (col0>>6) + wn;
    #pragma unroll
    for (int mt=0; mt<4; mt++) {
        #pragma unroll
        for (int hf=0; hf<2; hf++) {
            int row = row0 + m0 + mt*16 + g + hf*8;
            int bb = row>>11, n = row&(SEQ-1);
            size_t base = (((size_t)(bb*NH + hgl))*SEQ + n)*DHD;
            #pragma unroll
            for (int nt=0; nt<8; nt++) {
                int dh = nt*8 + q*2;
                *(uint32_t*)(dst + base + dh) =
                    pkh(acc[mt][nt][hf*2+0]*scale, acc[mt][nt][hf*2+1]*scale);
            }
        }
    }
}

// ============================================================================
// Flash attention — R14 hot loop, persistent grid (296 workers, 1 wave).
// Worker w takes 3-4 CONSECUTIVE items (same head mostly -> K/V L2 reuse).
// Item = (b,h,q-tile of 64): 4 warps = 2wm x 2wn; 2 CTAs/SM.
// smem 72KB: Q@0 (8KB); 2 K/V stages @8K (k@0, v@16K per 32KB stage).
// ============================================================================
#define A_SMEM (8192 + 2*32768)
#define NWORK  1024
#define NWKR   296

__global__ __launch_bounds__(128,2) void attn(float* __restrict__ out)
{
    extern __shared__ char smem[];
    const uint32_t sb = smem_u32(smem);
    const int tid = threadIdx.x, lane = tid&31, wid = tid>>5;
    const int wm = wid>>1, wn = wid&1, m0 = wm*32;
    const uint32_t nb = wn*64*128;
    const int g = lane>>2, q = lane&3;

    // static schedule: first 136 workers get 4 items, rest get 3
    const int w = blockIdx.x;
    int start, cnt;
    if (w < NWORK - 3*NWKR ? 0 : 1) {}               // (computed below)
    {
        const int big = NWORK - 3*NWKR;              // 136
        if (w < big) { start = w*4;            cnt = 4; }
        else         { start = big*4 + (w-big)*3; cnt = 3; }
    }

    for (int it_i = 0; it_i < cnt; it_i++) {
        const int item = start + it_i;
        const int q0 = (item & 31) * 64;
        const int h  = (item >> 5) & 15;
        const int b  = item >> 9;
        const size_t hb = ((size_t)(b*NH + h))*SEQ;

        auto issueKV = [&](int kt){
            uint32_t base = sb + 8192 + (kt&1)*32768;
            const int k0 = kt*128;
            #pragma unroll
            for (int it=0; it<8; it++) {
                int i = tid + it*128;
                int r = i>>3, c8 = (i&7)*8;
                uint32_t off = SW(r*128 + c8*2);
                size_t gofs = (hb + k0 + r)*DHD + c8;
                cpa(base + off,         g_k + gofs);
                cpa(base + 16384 + off, g_v + gofs);
            }
            cpcommit();
        };

        issueKV(0);
        #pragma unroll
        for (int it=0; it<4; it++) {               // Q tile: 64 rows (8KB)
            int i = tid + it*128;
            int r = i>>3, c8 = (i&7)*8;
            *(uint4*)(smem + SW(r*128 + c8*2)) = *(const uint4*)(g_q + (hb+q0+r)*DHD + c8);
        }
        __syncthreads();

        uint32_t qf[2][4][4];
        #pragma unroll
        for (int mt=0; mt<2; mt++)
            #pragma unroll
            for (int ks=0; ks<4; ks++) {
                uint32_t ao = (uint32_t)((m0 + mt*16 + (lane&7) + ((lane>>3)&1)*8)*128
                                          + ks*32 + ((lane>>4)&1)*16);
                ldsm4(qf[mt][ks], sb + SW(ao));
            }

        float o[2][8][4];
        #pragma unroll
        for (int m=0;m<2;m++) for (int a=0;a<8;a++) for (int c=0;c<4;c++) o[m][a][c]=0.f;
        float rs[2][2] = {{0.f,0.f},{0.f,0.f}};

        for (int kt=0; kt<16; kt++) {
            if (kt<15) { issueKV(kt+1); cpwait<1>(); } else cpwait<0>();
            __syncthreads();
            const uint32_t sk = sb + 8192 + (kt&1)*32768;

            float s[2][8][4];
            #pragma unroll
            for (int m=0;m<2;m++) for (int a=0;a<8;a++) for (int c=0;c<4;c++) s[m][a][c]=0.f;
            #pragma unroll
            for (int ks=0; ks<4; ks++) {
                #pragma unroll
                for (int pr=0; pr<4; pr++) {
                    uint32_t kf[4];
                    uint32_t bo = (uint32_t)(nb + (pr*16 + (lane&7) + ((lane>>4)&1)*8)*128
                                              + ks*32 + ((lane>>3)&1)*16);
                    ldsm4(kf, sk + SW(bo));
                    #pragma unroll
                    for (int mt=0; mt<2; mt++) {
                        mmah(s[mt][2*pr],   qf[mt][ks], kf);
                        mmah(s[mt][2*pr+1], qf[mt][ks], kf+2);
                    }
                }
            }

            #pragma unroll
            for (int ks=0; ks<4; ks++) {
                uint32_t pf[2][4];
                #pragma unroll
                for (int mt=0; mt<2; mt++) {
                    pf[mt][0] = ex2h2(pkh(s[mt][2*ks][0],   s[mt][2*ks][1]));
                    pf[mt][1] = ex2h2(pkh(s[mt][2*ks][2],   s[mt][2*ks][3]));
                    pf[mt][2] = ex2h2(pkh(s[mt][2*ks+1][0], s[mt][2*ks+1][1]));
                    pf[mt][3] = ex2h2(pkh(s[mt][2*ks+1][2], s[mt][2*ks+1][3]));
                    __half2 hg  = __hadd2(*(__half2*)&pf[mt][0], *(__half2*)&pf[mt][2]);
                    __half2 hg8 = __hadd2(*(__half2*)&pf[mt][1], *(__half2*)&pf[mt][3]);
                    float2 fg  = __half22float2(hg);
                    float2 fg8 = __half22float2(hg8);
                    rs[mt][0] += fg.x  + fg.y;
                    rs[mt][1] += fg8.x + fg8.y;
                }
                #pragma unroll
                for (int pr=0; pr<4; pr++) {
                    uint32_t vf[4];
                    uint32_t vo = (uint32_t)(nb + (ks*16 + (lane&7) + ((lane>>3)&1)*8)*128
                                              + pr*32 + ((lane>>4)&1)*16);
                    ldsm4t(vf, sk + 16384 + SW(vo));
                    #pragma unroll
                    for (int mt=0; mt<2; mt++) {
                        mmah(o[mt][2*pr],   pf[mt], vf);
                        mmah(o[mt][2*pr+1], pf[mt], vf+2);
                    }
                }
            }
            __syncthreads();
        }

        // quad reduction of rowsums, combine across the wn pair
        #pragma unroll
        for (int mt=0; mt<2; mt++) {
            rs[mt][0] += __shfl_xor_sync(0xffffffffu, rs[mt][0], 1);
            rs[mt][0] += __shfl_xor_sync(0xffffffffu, rs[mt][0], 2);
            rs[mt][1] += __shfl_xor_sync(0xffffffffu, rs[mt][1], 1);
            rs[mt][1] += __shfl_xor_sync(0xffffffffu, rs[mt][1], 2);
        }

        float* rsArr = (float*)smem;                        // [2][64] (Q region)
        float* Osum  = (float*)(smem + 8192) + wm*2048;     // per-wm [32][64]
        if ((lane&3)==0) {
            #pragma unroll
            for (int mt=0; mt<2; mt++) {
                rsArr[wn*64 + m0 + mt*16 + g]     = rs[mt][0];
                rsArr[wn*64 + m0 + mt*16 + 8 + g] = rs[mt][1];
            }
        }
        if (wn==1) {
            #pragma unroll
            for (int mt=0; mt<2; mt++)
                #pragma unroll
                for (int nt=0; nt<8; nt++) {
                    *(float2*)&Osum[(mt*16+g)*64   + nt*8 + q*2] = make_float2(o[mt][nt][0], o[mt][nt][1]);
                    *(float2*)&Osum[(mt*16+g+8)*64 + nt*8 + q*2] = make_float2(o[mt][nt][2], o[mt][nt][3]);
                }
        }
        __syncthreads();
        if (wn==0) {
            #pragma unroll
            for (int mt=0; mt<2; mt++) {
                const int r0 = m0 + mt*16 + g;
                const float i0 = 1.0f/(rsArr[r0]     + rsArr[64+r0]);
                const float i1 = 1.0f/(rsArr[r0+8]   + rsArr[64+r0+8]);
                float* op0 = out + ((size_t)b*SEQ + q0 + r0)*EMB + h*DHD;
                float* op1 = op0 + (size_t)8*EMB;
                #pragma unroll
                for (int nt=0; nt<8; nt++) {
                    int dh = nt*8 + q*2;
                    float2 v0 = *(float2*)&Osum[(mt*16+g)*64   + dh];
                    float2 v1 = *(float2*)&Osum[(mt*16+g+8)*64 + dh];
                    *(float2*)(op0 + dh) = make_float2((o[mt][nt][0]+v0.x)*i0, (o[mt][nt][1]+v0.y)*i0);
                    *(float2*)(op1 + dh) = make_float2((o[mt][nt][2]+v1.x)*i1, (o[mt][nt][3]+v1.y)*i1);
                }
            }
        }
        __syncthreads();   // protect smem reuse by next item
    }
}

// ---------------------------------------------------------------------------
extern "C" void kernel_launch(void* const* d_in, const int* in_sizes, int n_in,
                              void* d_out, int out_size)
{
    const float* x  = (const float*)d_in[0];
    const float* wq = (const float*)d_in[1];
    const float* wk = (const float*)d_in[2];
    const float* wv = (const float*)d_in[3];
    float* out = (float*)d_out;

    cudaFuncSetAttribute(qkv_gemm, cudaFuncAttributeMaxDynamicSharedMemorySize, G_SMEM);
    cudaFuncSetAttribute(attn,     cudaFuncAttributeMaxDynamicSharedMemorySize, A_SMEM);

    __half *xp, *wp;
    cudaGetSymbolAddress((void**)&xp, g_x);
    cudaGetSymbolAddress((void**)&wp, g_w);

    dim3 gc(1024, 7);
    cvt_all<<<gc, 256>>>(x, wq, wk, wv, xp, wp);

    dim3 gg(EMB/128, (BATCH*SEQ)/128, 3);
    qkv_gemm<<<gg, 128, G_SMEM>>>();

    attn<<<NWKR, 128, A_SMEM>>>(out);
}